// round 1
// baseline (speedup 1.0000x reference)
#include <cuda_runtime.h>
#include <math.h>

// Problem constants
#define Bq   4
#define Tq   4096
#define Hh   8
#define Dd   32
#define HIDq 512
#define NC   1040            // packed projection columns: q256 k256 v256 w256 beta8 g8
#define MROWS (Bq*Tq)        // 16384
#define BH   (Bq*Hh)         // 32

// -------------------- scratch (device globals; no allocation) --------------------
__device__ float  g_W[NC * HIDq];                       // packed weights (2.1 MB)
__device__ float  g_Y[(size_t)MROWS * NC];              // projection output (68 MB)
__device__ float2 g_wv[(size_t)BH * Tq * Dd];           // (w,v) streams (33.5 MB)
__device__ float4 g_scal[(size_t)BH * Tq * Dd];         // (k, q*scale*eg, beta, 0) (67 MB)
__device__ float  g_att[(size_t)MROWS * (Hh*Dd)];       // attention output (16.8 MB)

// -------------------- weight packing --------------------
__global__ void packW(const float* __restrict__ wq, const float* __restrict__ wk,
                      const float* __restrict__ wv, const float* __restrict__ ww,
                      const float* __restrict__ wb, const float* __restrict__ wg) {
    int i = blockIdx.x * 256 + threadIdx.x;
    if (i >= NC * HIDq) return;
    int r = i / HIDq, c = i % HIDq;
    float v;
    if      (r < 256)  v = wq[i];
    else if (r < 512)  v = wk[(r - 256)  * HIDq + c];
    else if (r < 768)  v = wv[(r - 512)  * HIDq + c];
    else if (r < 1024) v = ww[(r - 768)  * HIDq + c];
    else if (r < 1032) v = wb[(r - 1024) * HIDq + c];
    else               v = wg[(r - 1032) * HIDq + c];
    g_W[i] = v;
}

// -------------------- SIMT SGEMM: C[M,N] = A[M,K] * B[N,K]^T --------------------
// 128x128 tile, BK=8, 256 threads, 8x8 per thread. M must be a multiple of 128,
// K a multiple of 8. N guarded. epi=1 applies sigmoid activations on cols >=1024.
__global__ void __launch_bounds__(256)
sgemm(const float* __restrict__ A, const float* __restrict__ B,
      float* __restrict__ C, int M, int N, int K, int epi,
      const float* __restrict__ bbeta, const float* __restrict__ bg) {
    __shared__ float As[8][128];
    __shared__ float Bs[8][128];
    const int tid  = threadIdx.x;
    const int brow = blockIdx.y * 128;
    const int bcol = blockIdx.x * 128;
    const int lr = tid >> 1;             // 0..127
    const int lc = (tid & 1) << 2;       // 0 or 4
    const int tx = tid & 15, ty = tid >> 4;

    float acc[8][8];
#pragma unroll
    for (int i = 0; i < 8; ++i)
#pragma unroll
        for (int j = 0; j < 8; ++j) acc[i][j] = 0.f;

    for (int kt = 0; kt < K; kt += 8) {
        float4 a4 = *(const float4*)(A + (size_t)(brow + lr) * K + kt + lc);
        float4 b4 = make_float4(0.f, 0.f, 0.f, 0.f);
        int bn = bcol + lr;
        if (bn < N) b4 = *(const float4*)(B + (size_t)bn * K + kt + lc);
        As[lc + 0][lr] = a4.x; As[lc + 1][lr] = a4.y;
        As[lc + 2][lr] = a4.z; As[lc + 3][lr] = a4.w;
        Bs[lc + 0][lr] = b4.x; Bs[lc + 1][lr] = b4.y;
        Bs[lc + 2][lr] = b4.z; Bs[lc + 3][lr] = b4.w;
        __syncthreads();
#pragma unroll
        for (int kk = 0; kk < 8; ++kk) {
            float ar[8], br[8];
            *(float4*)(ar)     = *(const float4*)&As[kk][ty * 8];
            *(float4*)(ar + 4) = *(const float4*)&As[kk][ty * 8 + 4];
            *(float4*)(br)     = *(const float4*)&Bs[kk][tx * 8];
            *(float4*)(br + 4) = *(const float4*)&Bs[kk][tx * 8 + 4];
#pragma unroll
            for (int i = 0; i < 8; ++i)
#pragma unroll
                for (int j = 0; j < 8; ++j)
                    acc[i][j] = fmaf(ar[i], br[j], acc[i][j]);
        }
        __syncthreads();
    }

#pragma unroll
    for (int i = 0; i < 8; ++i) {
        int gm = brow + ty * 8 + i;
#pragma unroll
        for (int j = 0; j < 8; ++j) {
            int gn = bcol + tx * 8 + j;
            if (gn < N) {
                float val = acc[i][j];
                if (epi && gn >= 1024) {
                    if (gn < 1032) {
                        // beta = 2 * sigmoid(z + bbeta)
                        val = 2.f / (1.f + expf(-(val + bbeta[gn - 1024])));
                    } else {
                        // store exp(log_sigmoid(z)) = sigmoid(z + bg) directly
                        val = 1.f / (1.f + expf(-(val + bg[gn - 1032])));
                    }
                }
                C[(size_t)gm * N + gn] = val;
            }
        }
    }
}

// -------------------- prep: normalize w, fold q*scale*eg, pack streams --------------------
// one warp per (bh, t): lane covers the D=32 dimension.
__global__ void __launch_bounds__(256) prep() {
    const float scale = 0.17677669529663687f;   // 32^-0.5
    int g    = blockIdx.x * 8 + (threadIdx.x >> 5);  // 0..131071
    int lane = threadIdx.x & 31;
    int bh = g >> 12;            // /4096
    int t  = g & 4095;
    int b = bh >> 3, h = bh & 7;
    const float* r = g_Y + (size_t)(b * Tq + t) * NC;

    float w = r[768 + h * 32 + lane];
    float ss = w * w;
    ss += __shfl_xor_sync(0xffffffffu, ss, 16);
    ss += __shfl_xor_sync(0xffffffffu, ss, 8);
    ss += __shfl_xor_sync(0xffffffffu, ss, 4);
    ss += __shfl_xor_sync(0xffffffffu, ss, 2);
    ss += __shfl_xor_sync(0xffffffffu, ss, 1);
    w = w / (sqrtf(ss) + 1e-6f);

    float v    = r[512 + h * 32 + lane];
    float k    = r[256 + h * 32 + lane];
    float q    = r[       h * 32 + lane];
    float beta = r[1024 + h];
    float eg   = r[1032 + h];   // = exp(log_sigmoid(zg)) = sigmoid(zg)

    size_t o = (size_t)g * 32 + lane;
    g_wv[o]   = make_float2(w, v);
    g_scal[o] = make_float4(k, q * scale * eg, beta, 0.f);
}

// -------------------- recurrence --------------------
// 32 blocks (one per (b,h)), 1024 threads: warp = state row d, lane = column m.
// Each thread keeps a single state element S[d][m] in a register.
// S_t = S_{t-1}(I - beta w w^T) + k v^T ; out[m] = sum_d (q*scale*eg)[d] * S[d][m]
__global__ void __launch_bounds__(1024, 1) recur() {
    __shared__ float  part[8][32][33];
    __shared__ float2 s_wv[8][32];
    __shared__ float4 s_sc[8][32];

    const int bh = blockIdx.x;
    const int b = bh >> 3, h = bh & 7;
    const int tid = threadIdx.x;
    const int d = tid >> 5, m = tid & 31;
    const size_t sbase = (size_t)bh * Tq * 32;

    float S = 0.f;

    // preload window 0
    if (tid < 256) {
        int tw = tid >> 5, mm = tid & 31;
        s_wv[tw][mm] = g_wv[sbase + (size_t)tw * 32 + mm];
    } else if (tid < 512) {
        int u = tid - 256;
        int tw = u >> 5, dd = u & 31;
        s_sc[tw][dd] = g_scal[sbase + (size_t)tw * 32 + dd];
    }
    __syncthreads();

    for (int t0 = 0; t0 < Tq; t0 += 8) {
#pragma unroll
        for (int tw = 0; tw < 8; ++tw) {
            float2 wvv = s_wv[tw][m];
            float4 sc  = s_sc[tw][d];
            float p = S * wvv.x;                          // S[d][m]*w[m]
            p += __shfl_xor_sync(0xffffffffu, p, 16);
            p += __shfl_xor_sync(0xffffffffu, p, 8);
            p += __shfl_xor_sync(0xffffffffu, p, 4);
            p += __shfl_xor_sync(0xffffffffu, p, 2);
            p += __shfl_xor_sync(0xffffffffu, p, 1);      // Sw[d]
            S = fmaf(-sc.z * p, wvv.x, S);                // -beta*Sw[d]*w[m]
            S = fmaf(sc.x, wvv.y, S);                     // +k[d]*v[m]
            part[tw][d][m] = sc.y * S;                    // (q*scale*eg)[d]*S
        }
        __syncthreads();
        if (tid < 256) {
            // reduce over d for the 8 steps just computed
            int tw = tid >> 5, mm = tid & 31;
            float s0 = 0.f, s1 = 0.f;
#pragma unroll
            for (int dd = 0; dd < 32; dd += 2) {
                s0 += part[tw][dd][mm];
                s1 += part[tw][dd + 1][mm];
            }
            g_att[(size_t)(b * Tq + t0 + tw) * 256 + h * 32 + mm] = s0 + s1;
        } else if (tid < 512 && t0 + 8 < Tq) {
            int u = tid - 256;
            int tw = u >> 5, mm = u & 31;
            s_wv[tw][mm] = g_wv[sbase + (size_t)(t0 + 8 + tw) * 32 + mm];
        } else if (tid < 768 && t0 + 8 < Tq) {
            int u = tid - 512;
            int tw = u >> 5, dd = u & 31;
            s_sc[tw][dd] = g_scal[sbase + (size_t)(t0 + 8 + tw) * 32 + dd];
        }
        __syncthreads();
    }
}

// -------------------- launch --------------------
extern "C" void kernel_launch(void* const* d_in, const int* in_sizes, int n_in,
                              void* d_out, int out_size) {
    const float* x     = (const float*)d_in[0];
    const float* Wq    = (const float*)d_in[1];
    const float* Wk    = (const float*)d_in[2];
    const float* Wv    = (const float*)d_in[3];
    const float* Ww    = (const float*)d_in[4];
    const float* Wbeta = (const float*)d_in[5];
    const float* bbeta = (const float*)d_in[6];
    const float* Wg    = (const float*)d_in[7];
    const float* bg    = (const float*)d_in[8];
    const float* Wo    = (const float*)d_in[9];
    float* out = (float*)d_out;

    void *pY, *pAtt;
    cudaGetSymbolAddress(&pY,   g_Y);
    cudaGetSymbolAddress(&pAtt, g_att);
    float* Y   = (float*)pY;
    float* att = (float*)pAtt;
    // g_W accessed directly by sgemm via symbol address
    void* pW;
    cudaGetSymbolAddress(&pW, g_W);
    float* W = (float*)pW;

    // 1) pack weights
    packW<<<(NC * HIDq + 255) / 256, 256>>>(Wq, Wk, Wv, Ww, Wbeta, Wg);

    // 2) fused projection GEMM + activations: Y[16384,1040] = x @ W^T
    sgemm<<<dim3(9, 128), 256>>>(x, W, Y, MROWS, NC, HIDq, 1, bbeta, bg);

    // 3) normalize w, fold scales, pack recurrence streams
    prep<<<16384, 256>>>();

    // 4) sequential state recurrence
    recur<<<BH, 1024>>>();

    // 5) output projection: out[16384,512] = att @ Wo^T
    sgemm<<<dim3(4, 128), 256>>>(att, Wo, out, MROWS, HIDq, Hh * Dd, 0, nullptr, nullptr);
}